// round 3
// baseline (speedup 1.0000x reference)
#include <cuda_runtime.h>
#include <cuda_bf16.h>
#include <cstdint>

// ---------------------------------------------------------------------------
// Problem constants
// ---------------------------------------------------------------------------
#define BATCH   8
#define LQ      2048
#define LK      2048
#define IMG_DIM 1024
#define TXT_DIM 768
#define HID     1024

#define MQ (BATCH * LQ)   // 16384 rows of Q
#define MK (BATCH * LK)   // 16384 rows of K/V

#define ZCHUNK  2         // batches processed per scores-buffer pass
#define NCHUNK  (BATCH / ZCHUNK)

// Scratch (static device globals — allocation-free per harness rules)
// Total static: 64 + 64 + 64 + 32 = 224 MB (down from 320 MB in prior round)
__device__ float g_Q[(size_t)MQ * HID];                   // 64 MB
__device__ float g_K[(size_t)MK * HID];                   // 64 MB
__device__ float g_V[(size_t)MK * HID];                   // 64 MB
__device__ float g_S[(size_t)ZCHUNK * LQ * LK];           // 32 MB (reused 4x)

// ---------------------------------------------------------------------------
// TF32 helpers
// ---------------------------------------------------------------------------
__device__ __forceinline__ unsigned f2tf32(float f) {
    unsigned r;
    asm("cvt.rna.tf32.f32 %0, %1;" : "=r"(r) : "f"(f));
    return r;
}

__device__ __forceinline__ void mma_tf32(float* d, const unsigned* a, const unsigned* b) {
    asm volatile(
        "mma.sync.aligned.m16n8k8.row.col.f32.tf32.tf32.f32 "
        "{%0,%1,%2,%3}, {%4,%5,%6,%7}, {%8,%9}, {%0,%1,%2,%3};"
        : "+f"(d[0]), "+f"(d[1]), "+f"(d[2]), "+f"(d[3])
        : "r"(a[0]), "r"(a[1]), "r"(a[2]), "r"(a[3]),
          "r"(b[0]), "r"(b[1]));
}

// ---------------------------------------------------------------------------
// Generic TF32 GEMM: C[z] = alpha * A[z] @ op(B[z]) + bias
//   A row-major [M,K]; TRANS_B ? B row-major [N,K] (A@B^T) : B row-major [K,N]
// Tile: BM=128, BN=128, BK=32; 256 threads, 8 warps (4 M x 2 N),
// warp tile 32x64. Requires M%128==0, N%128==0, K%32==0.
// ---------------------------------------------------------------------------
template <bool TRANS_B, bool HAS_BIAS>
__global__ __launch_bounds__(256, 2)
void gemm_tf32_kernel(const float* __restrict__ A, const float* __restrict__ Bm,
                      const float* __restrict__ bias, float* __restrict__ C,
                      int M, int N, int K, int lda, int ldb, int ldc,
                      long strideA, long strideB, long strideC, float alpha)
{
    constexpr int BM = 128, BN = 128, BK = 32;
    __shared__ unsigned As[BM][BK + 4];
    __shared__ unsigned Bs[TRANS_B ? BN : BK][TRANS_B ? (BK + 4) : (BN + 4)];

    const int bz = blockIdx.z;
    A  += (long)bz * strideA;
    Bm += (long)bz * strideB;
    C  += (long)bz * strideC;

    const int m0 = blockIdx.y * BM;
    const int n0 = blockIdx.x * BN;

    const int tid  = threadIdx.x;
    const int lane = tid & 31;
    const int warp = tid >> 5;
    const int gid  = lane >> 2;
    const int tid4 = lane & 3;
    const int wm   = warp & 3;
    const int wn   = warp >> 2;

    float acc[2][8][4] = {};

    for (int k0 = 0; k0 < K; k0 += BK) {
        #pragma unroll
        for (int i = 0; i < 4; i++) {
            int linear = tid + i * 256;
            int row = linear >> 3;
            int kk  = (linear & 7) << 2;
            float4 v = *reinterpret_cast<const float4*>(&A[(long)(m0 + row) * lda + k0 + kk]);
            As[row][kk + 0] = f2tf32(v.x);
            As[row][kk + 1] = f2tf32(v.y);
            As[row][kk + 2] = f2tf32(v.z);
            As[row][kk + 3] = f2tf32(v.w);
        }
        if (TRANS_B) {
            #pragma unroll
            for (int i = 0; i < 4; i++) {
                int linear = tid + i * 256;
                int row = linear >> 3;
                int kk  = (linear & 7) << 2;
                float4 v = *reinterpret_cast<const float4*>(&Bm[(long)(n0 + row) * ldb + k0 + kk]);
                Bs[row][kk + 0] = f2tf32(v.x);
                Bs[row][kk + 1] = f2tf32(v.y);
                Bs[row][kk + 2] = f2tf32(v.z);
                Bs[row][kk + 3] = f2tf32(v.w);
            }
        } else {
            #pragma unroll
            for (int i = 0; i < 4; i++) {
                int linear = tid + i * 256;
                int row = linear >> 5;
                int nn  = (linear & 31) << 2;
                float4 v = *reinterpret_cast<const float4*>(&Bm[(long)(k0 + row) * ldb + n0 + nn]);
                Bs[row][nn + 0] = f2tf32(v.x);
                Bs[row][nn + 1] = f2tf32(v.y);
                Bs[row][nn + 2] = f2tf32(v.z);
                Bs[row][nn + 3] = f2tf32(v.w);
            }
        }
        __syncthreads();

        #pragma unroll
        for (int ks = 0; ks < BK / 8; ks++) {
            const int k8 = ks * 8;
            unsigned af[2][4], bf[8][2];
            #pragma unroll
            for (int mt = 0; mt < 2; mt++) {
                int r = wm * 32 + mt * 16 + gid;
                af[mt][0] = As[r][k8 + tid4];
                af[mt][1] = As[r + 8][k8 + tid4];
                af[mt][2] = As[r][k8 + tid4 + 4];
                af[mt][3] = As[r + 8][k8 + tid4 + 4];
            }
            #pragma unroll
            for (int nt = 0; nt < 8; nt++) {
                int n = wn * 64 + nt * 8 + gid;
                if (TRANS_B) {
                    bf[nt][0] = Bs[n][k8 + tid4];
                    bf[nt][1] = Bs[n][k8 + tid4 + 4];
                } else {
                    bf[nt][0] = Bs[k8 + tid4][n];
                    bf[nt][1] = Bs[k8 + tid4 + 4][n];
                }
            }
            #pragma unroll
            for (int mt = 0; mt < 2; mt++)
                #pragma unroll
                for (int nt = 0; nt < 8; nt++)
                    mma_tf32(acc[mt][nt], af[mt], bf[nt]);
        }
        __syncthreads();
    }

    #pragma unroll
    for (int mt = 0; mt < 2; mt++) {
        #pragma unroll
        for (int nt = 0; nt < 8; nt++) {
            int col = n0 + wn * 64 + nt * 8 + 2 * tid4;
            float b0 = 0.f, b1 = 0.f;
            if (HAS_BIAS) { b0 = bias[col]; b1 = bias[col + 1]; }
            int r0 = m0 + wm * 32 + mt * 16 + gid;
            float2 v0 = make_float2(alpha * acc[mt][nt][0] + b0,
                                    alpha * acc[mt][nt][1] + b1);
            float2 v1 = make_float2(alpha * acc[mt][nt][2] + b0,
                                    alpha * acc[mt][nt][3] + b1);
            *reinterpret_cast<float2*>(&C[(long)r0 * ldc + col])       = v0;
            *reinterpret_cast<float2*>(&C[(long)(r0 + 8) * ldc + col]) = v1;
        }
    }
}

// ---------------------------------------------------------------------------
// Fused online-softmax + PV GEMM.
//   O[z] = softmax_rows(S[z]) @ V[z]
// S holds raw scaled scores (alpha already applied by the QK^T GEMM).
// grid: (HID/128, LQ/128, ZCHUNK); 256 threads.
// Per k-tile (BK=32): thread pair (tid>>1 = row) owns one of the 128 q-rows,
// maintains running max m and sum l in registers, writes exp(s-m) to smem,
// and publishes the accumulator rescale factor via smem.
// ---------------------------------------------------------------------------
__global__ __launch_bounds__(256, 2)
void attn_pv_online(const float* __restrict__ S, const float* __restrict__ V,
                    float* __restrict__ O)
{
    constexpr int BM = 128, BN = 128, BK = 32;
    __shared__ float    As[BM][BK + 4];    // exp'd scores (float)
    __shared__ unsigned Bs[BK][BN + 4];    // V tile (tf32 bits)
    __shared__ float    scaleArr[BM];
    __shared__ float    lArr[BM];

    const int z = blockIdx.z;
    S += (long)z * LQ * LK;
    V += (long)z * LK * HID;
    O += (long)z * LQ * HID;

    const int m0 = blockIdx.y * BM;
    const int n0 = blockIdx.x * BN;

    const int tid  = threadIdx.x;
    const int lane = tid & 31;
    const int warp = tid >> 5;
    const int gid  = lane >> 2;
    const int tid4 = lane & 3;
    const int wm   = warp & 3;
    const int wn   = warp >> 2;

    const int srow = tid >> 1;          // q-row owned by this thread pair
    const int scol = (tid & 1) * 16;    // half-row offset

    float m_run = -INFINITY;
    float l_run = 0.f;

    float acc[2][8][4] = {};

    for (int k0 = 0; k0 < LK; k0 += BK) {
        // ---- load this thread's 16 raw scores ----
        float sv[16];
        const float* srcS = &S[(long)(m0 + srow) * LK + k0 + scol];
        #pragma unroll
        for (int i = 0; i < 4; i++) {
            float4 v = reinterpret_cast<const float4*>(srcS)[i];
            sv[4*i+0] = v.x; sv[4*i+1] = v.y; sv[4*i+2] = v.z; sv[4*i+3] = v.w;
        }
        // ---- load V tile [32 k][128 n] ----
        #pragma unroll
        for (int i = 0; i < 4; i++) {
            int linear = tid + i * 256;
            int row = linear >> 5;
            int nn  = (linear & 31) << 2;
            float4 v = *reinterpret_cast<const float4*>(&V[(long)(k0 + row) * HID + n0 + nn]);
            Bs[row][nn + 0] = f2tf32(v.x);
            Bs[row][nn + 1] = f2tf32(v.y);
            Bs[row][nn + 2] = f2tf32(v.z);
            Bs[row][nn + 3] = f2tf32(v.w);
        }

        // ---- online softmax update for this row's 32-wide chunk ----
        float mx = sv[0];
        #pragma unroll
        for (int i = 1; i < 16; i++) mx = fmaxf(mx, sv[i]);
        mx = fmaxf(mx, __shfl_xor_sync(0xffffffffu, mx, 1));
        float m_new = fmaxf(m_run, mx);
        float scale = __expf(m_run - m_new);      // first iter: exp(-inf)=0
        float ps = 0.f;
        #pragma unroll
        for (int i = 0; i < 16; i++) { sv[i] = __expf(sv[i] - m_new); ps += sv[i]; }
        ps += __shfl_xor_sync(0xffffffffu, ps, 1);
        l_run = l_run * scale + ps;
        m_run = m_new;
        #pragma unroll
        for (int i = 0; i < 16; i++) As[srow][scol + i] = sv[i];
        if ((tid & 1) == 0) scaleArr[srow] = scale;
        __syncthreads();

        // ---- rescale accumulators by per-row factor ----
        #pragma unroll
        for (int mt = 0; mt < 2; mt++) {
            int r = wm * 32 + mt * 16 + gid;
            float s0 = scaleArr[r];
            float s1 = scaleArr[r + 8];
            #pragma unroll
            for (int nt = 0; nt < 8; nt++) {
                acc[mt][nt][0] *= s0; acc[mt][nt][1] *= s0;
                acc[mt][nt][2] *= s1; acc[mt][nt][3] *= s1;
            }
        }

        // ---- accumulate P @ V for this k-tile ----
        #pragma unroll
        for (int ks = 0; ks < BK / 8; ks++) {
            const int k8 = ks * 8;
            unsigned af[2][4], bf[8][2];
            #pragma unroll
            for (int mt = 0; mt < 2; mt++) {
                int r = wm * 32 + mt * 16 + gid;
                af[mt][0] = f2tf32(As[r][k8 + tid4]);
                af[mt][1] = f2tf32(As[r + 8][k8 + tid4]);
                af[mt][2] = f2tf32(As[r][k8 + tid4 + 4]);
                af[mt][3] = f2tf32(As[r + 8][k8 + tid4 + 4]);
            }
            #pragma unroll
            for (int nt = 0; nt < 8; nt++) {
                int n = wn * 64 + nt * 8 + gid;
                bf[nt][0] = Bs[k8 + tid4][n];
                bf[nt][1] = Bs[k8 + tid4 + 4][n];
            }
            #pragma unroll
            for (int mt = 0; mt < 2; mt++)
                #pragma unroll
                for (int nt = 0; nt < 8; nt++)
                    mma_tf32(acc[mt][nt], af[mt], bf[nt]);
        }
        __syncthreads();
    }

    // ---- publish row sums, normalize, write out ----
    if ((tid & 1) == 0) lArr[srow] = l_run;
    __syncthreads();

    #pragma unroll
    for (int mt = 0; mt < 2; mt++) {
        int r = wm * 32 + mt * 16 + gid;
        float inv0 = 1.0f / lArr[r];
        float inv1 = 1.0f / lArr[r + 8];
        #pragma unroll
        for (int nt = 0; nt < 8; nt++) {
            int col = n0 + wn * 64 + nt * 8 + 2 * tid4;
            int gr = m0 + r;
            float2 v0 = make_float2(acc[mt][nt][0] * inv0, acc[mt][nt][1] * inv0);
            float2 v1 = make_float2(acc[mt][nt][2] * inv1, acc[mt][nt][3] * inv1);
            *reinterpret_cast<float2*>(&O[(long)gr * HID + col])       = v0;
            *reinterpret_cast<float2*>(&O[(long)(gr + 8) * HID + col]) = v1;
        }
    }
}

// ---------------------------------------------------------------------------
// Launch
// ---------------------------------------------------------------------------
extern "C" void kernel_launch(void* const* d_in, const int* in_sizes, int n_in,
                              void* d_out, int out_size)
{
    const float* img = (const float*)d_in[0];
    const float* txt = (const float*)d_in[1];
    const float* Wq  = (const float*)d_in[2];
    const float* bq  = (const float*)d_in[3];
    const float* Wk  = (const float*)d_in[4];
    const float* bk  = (const float*)d_in[5];
    const float* Wv  = (const float*)d_in[6];
    const float* bv  = (const float*)d_in[7];
    float* out = (float*)d_out;

    float *Qb, *Kb, *Vb, *Sb;
    cudaGetSymbolAddress((void**)&Qb, g_Q);
    cudaGetSymbolAddress((void**)&Kb, g_K);
    cudaGetSymbolAddress((void**)&Vb, g_V);
    cudaGetSymbolAddress((void**)&Sb, g_S);

    const dim3 blk(256);

    // ---- Projections (flattened batch) ----
    gemm_tf32_kernel<false, true><<<dim3(HID / 128, MQ / 128, 1), blk>>>(
        img, Wq, bq, Qb, MQ, HID, IMG_DIM,
        IMG_DIM, HID, HID, 0, 0, 0, 1.0f);
    gemm_tf32_kernel<false, true><<<dim3(HID / 128, MK / 128, 1), blk>>>(
        txt, Wk, bk, Kb, MK, HID, TXT_DIM,
        TXT_DIM, HID, HID, 0, 0, 0, 1.0f);
    gemm_tf32_kernel<false, true><<<dim3(HID / 128, MK / 128, 1), blk>>>(
        txt, Wv, bv, Vb, MK, HID, TXT_DIM,
        TXT_DIM, HID, HID, 0, 0, 0, 1.0f);

    // ---- Attention, ZCHUNK batches at a time through the reusable S buffer.
    // Stream order serializes chunk c's PV (reads g_S) before chunk c+1's
    // S-GEMM (writes g_S); graph capture preserves this dependency.
    for (int c = 0; c < NCHUNK; c++) {
        const long zoff = (long)c * ZCHUNK;
        // S = (1/sqrt(HID)) * Q @ K^T   (batched NT within the chunk)
        gemm_tf32_kernel<true, false><<<dim3(LK / 128, LQ / 128, ZCHUNK), blk>>>(
            Qb + zoff * LQ * HID, Kb + zoff * LK * HID, nullptr, Sb,
            LQ, LK, HID,
            HID, HID, LK,
            (long)LQ * HID, (long)LK * HID, (long)LQ * LK,
            0.03125f /* 1/sqrt(1024) */);
        // O = softmax(S) @ V  (fused online softmax)
        attn_pv_online<<<dim3(HID / 128, LQ / 128, ZCHUNK), blk>>>(
            Sb, Vb + zoff * LK * HID, out + zoff * LQ * HID);
    }
}

// round 5
// speedup vs baseline: 1.7286x; 1.7286x over previous
#include <cuda_runtime.h>
#include <cuda_fp16.h>
#include <cstdint>

// ---------------------------------------------------------------------------
// Problem constants
// ---------------------------------------------------------------------------
#define BATCH   8
#define LQ      2048
#define LK      2048
#define IMG_DIM 1024
#define TXT_DIM 768
#define HID     1024

#define MQ (BATCH * LQ)
#define MK (BATCH * LK)

#define ZCHUNK  2
#define NCHUNK  (BATCH / ZCHUNK)

// ---------------------------------------------------------------------------
// Static scratch (~237 MB total)
// ---------------------------------------------------------------------------
__device__ __half g_img[(size_t)MQ * IMG_DIM];        // 32 MB
__device__ __half g_txt[(size_t)MK * TXT_DIM];        // 24 MB
__device__ __half g_Wqt[(size_t)HID * IMG_DIM];       // 2 MB   [HID][IMG]
__device__ __half g_Wkt[(size_t)HID * TXT_DIM];       // 1.5 MB [HID][TXT]
__device__ __half g_Wvt[(size_t)HID * TXT_DIM];       // 1.5 MB
__device__ __half g_Qh[(size_t)MQ * HID];             // 32 MB
__device__ __half g_Kh[(size_t)MK * HID];             // 32 MB
__device__ __half g_Vh[(size_t)MK * HID];             // 32 MB
__device__ __half g_Vt[(size_t)BATCH * HID * LK];     // 32 MB  [z][HID][LK]
__device__ float  g_S[(size_t)ZCHUNK * LQ * LK];      // 32 MB  (chunk, reused)
__device__ __half g_P[(size_t)ZCHUNK * LQ * LK];      // 16 MB  (chunk, reused)

// ---------------------------------------------------------------------------
// Helpers
// ---------------------------------------------------------------------------
__device__ __forceinline__ void cp16(void* dst, const void* src) {
    uint32_t s = (uint32_t)__cvta_generic_to_shared(dst);
    asm volatile("cp.async.cg.shared.global [%0], [%1], 16;" :: "r"(s), "l"(src));
}
#define CP_COMMIT() asm volatile("cp.async.commit_group;")
#define CP_WAIT1()  asm volatile("cp.async.wait_group 1;")

__device__ __forceinline__ void mma_f16(float* d, const uint32_t* a, const uint32_t* b) {
    asm volatile(
        "mma.sync.aligned.m16n8k16.row.col.f32.f16.f16.f32 "
        "{%0,%1,%2,%3}, {%4,%5,%6,%7}, {%8,%9}, {%0,%1,%2,%3};"
        : "+f"(d[0]), "+f"(d[1]), "+f"(d[2]), "+f"(d[3])
        : "r"(a[0]), "r"(a[1]), "r"(a[2]), "r"(a[3]),
          "r"(b[0]), "r"(b[1]));
}

// ---------------------------------------------------------------------------
// FP16 NT GEMM: C[z] = alpha * A[z] @ B[z]^T (+ bias)
//   A row-major [M][K] half, B row-major [N][K] half (both K-contiguous).
// Tile BM=BN=128, BK=32; 256 threads; cp.async double-buffered.
// Requires M,N % 128 == 0, K % 32 == 0, lda/ldb % 8 == 0.
// ---------------------------------------------------------------------------
template <bool HAS_BIAS, bool OUT_HALF>
__global__ __launch_bounds__(256, 2)
void gemm_f16_nt(const __half* __restrict__ A, const __half* __restrict__ B,
                 const float* __restrict__ bias, void* __restrict__ Cv,
                 int K, int lda, int ldb, int ldc,
                 long sA, long sB, long sC, float alpha)
{
    constexpr int BM = 128, BN = 128, BK = 32, LDT = 40;  // 40-half row stride
    __shared__ __half As[2][BM][LDT];
    __shared__ __half Bs[2][BN][LDT];

    const int bz = blockIdx.z;
    A += (long)bz * sA;
    B += (long)bz * sB;

    const int m0 = blockIdx.y * BM;
    const int n0 = blockIdx.x * BN;

    const int tid  = threadIdx.x;
    const int lane = tid & 31;
    const int warp = tid >> 5;
    const int gid  = lane >> 2;
    const int tid4 = lane & 3;
    const int wm   = warp & 3;
    const int wn   = warp >> 2;

    // tile loaders: 128 rows x 4 x 16B chunks each for A and B; 2+2 per thread
    const int r_ld = tid >> 1;
    const int s_ld = (tid & 1) * 2;

    float acc[2][8][4] = {};
    const int nk = K / BK;

    // prologue: tile 0
    {
        const __half* a0 = A + (long)(m0 + r_ld) * lda + s_ld * 8;
        const __half* b0 = B + (long)(n0 + r_ld) * ldb + s_ld * 8;
        cp16(&As[0][r_ld][s_ld * 8],      a0);
        cp16(&As[0][r_ld][s_ld * 8 + 8],  a0 + 8);
        cp16(&Bs[0][r_ld][s_ld * 8],      b0);
        cp16(&Bs[0][r_ld][s_ld * 8 + 8],  b0 + 8);
    }
    CP_COMMIT();

    for (int kt = 0; kt < nk; kt++) {
        const int cur = kt & 1;
        if (kt + 1 < nk) {
            const int k0 = (kt + 1) * BK;
            const __half* a0 = A + (long)(m0 + r_ld) * lda + k0 + s_ld * 8;
            const __half* b0 = B + (long)(n0 + r_ld) * ldb + k0 + s_ld * 8;
            cp16(&As[cur ^ 1][r_ld][s_ld * 8],     a0);
            cp16(&As[cur ^ 1][r_ld][s_ld * 8 + 8], a0 + 8);
            cp16(&Bs[cur ^ 1][r_ld][s_ld * 8],     b0);
            cp16(&Bs[cur ^ 1][r_ld][s_ld * 8 + 8], b0 + 8);
        }
        CP_COMMIT();
        CP_WAIT1();
        __syncthreads();

        #pragma unroll
        for (int ks = 0; ks < 2; ks++) {
            const int kk = ks * 16;
            uint32_t af[2][4], bf[8][2];
            #pragma unroll
            for (int mt = 0; mt < 2; mt++) {
                int r = wm * 32 + mt * 16 + gid;
                af[mt][0] = *(const uint32_t*)&As[cur][r][kk + 2 * tid4];
                af[mt][1] = *(const uint32_t*)&As[cur][r + 8][kk + 2 * tid4];
                af[mt][2] = *(const uint32_t*)&As[cur][r][kk + 2 * tid4 + 8];
                af[mt][3] = *(const uint32_t*)&As[cur][r + 8][kk + 2 * tid4 + 8];
            }
            #pragma unroll
            for (int nt = 0; nt < 8; nt++) {
                int n = wn * 64 + nt * 8 + gid;
                bf[nt][0] = *(const uint32_t*)&Bs[cur][n][kk + 2 * tid4];
                bf[nt][1] = *(const uint32_t*)&Bs[cur][n][kk + 2 * tid4 + 8];
            }
            #pragma unroll
            for (int mt = 0; mt < 2; mt++)
                #pragma unroll
                for (int nt = 0; nt < 8; nt++)
                    mma_f16(acc[mt][nt], af[mt], bf[nt]);
        }
        __syncthreads();
    }

    // ---- epilogue ----
    #pragma unroll
    for (int mt = 0; mt < 2; mt++) {
        #pragma unroll
        for (int nt = 0; nt < 8; nt++) {
            const int col = n0 + wn * 64 + nt * 8 + 2 * tid4;
            float b0 = 0.f, b1 = 0.f;
            if (HAS_BIAS) { b0 = bias[col]; b1 = bias[col + 1]; }
            const int r0 = m0 + wm * 32 + mt * 16 + gid;
            float v00 = alpha * acc[mt][nt][0] + b0;
            float v01 = alpha * acc[mt][nt][1] + b1;
            float v10 = alpha * acc[mt][nt][2] + b0;
            float v11 = alpha * acc[mt][nt][3] + b1;
            if (OUT_HALF) {
                __half* C = (__half*)Cv + (long)bz * sC;
                __half2 h0 = __floats2half2_rn(v00, v01);
                __half2 h1 = __floats2half2_rn(v10, v11);
                *reinterpret_cast<__half2*>(&C[(long)r0 * ldc + col])       = h0;
                *reinterpret_cast<__half2*>(&C[(long)(r0 + 8) * ldc + col]) = h1;
            } else {
                float* C = (float*)Cv + (long)bz * sC;
                *reinterpret_cast<float2*>(&C[(long)r0 * ldc + col])       = make_float2(v00, v01);
                *reinterpret_cast<float2*>(&C[(long)(r0 + 8) * ldc + col]) = make_float2(v10, v11);
            }
        }
    }
}

// ---------------------------------------------------------------------------
// float -> half elementwise (n4 float4 groups)
// ---------------------------------------------------------------------------
__global__ __launch_bounds__(256)
void f2h_kernel(const float* __restrict__ s, __half* __restrict__ d, long n4)
{
    long i = blockIdx.x * (long)blockDim.x + threadIdx.x;
    if (i < n4) {
        float4 v = reinterpret_cast<const float4*>(s)[i];
        __half2 h0 = __floats2half2_rn(v.x, v.y);
        __half2 h1 = __floats2half2_rn(v.z, v.w);
        uint2 u;
        u.x = *reinterpret_cast<uint32_t*>(&h0);
        u.y = *reinterpret_cast<uint32_t*>(&h1);
        reinterpret_cast<uint2*>(d)[i] = u;
    }
}

// ---------------------------------------------------------------------------
// Weight transpose + convert: src float [R][C] -> dst half [C][R]
// ---------------------------------------------------------------------------
__global__ __launch_bounds__(256)
void transpose_f2h(const float* __restrict__ src, __half* __restrict__ dst,
                   int R, int C)
{
    __shared__ float t[32][33];
    const int tx = threadIdx.x, ty = threadIdx.y;
    const int xb = blockIdx.x * 32, yb = blockIdx.y * 32;
    #pragma unroll
    for (int j = 0; j < 4; j++)
        t[ty + 8 * j][tx] = src[(long)(yb + ty + 8 * j) * C + xb + tx];
    __syncthreads();
    #pragma unroll
    for (int j = 0; j < 4; j++)
        dst[(long)(xb + ty + 8 * j) * R + yb + tx] = __float2half(t[tx][ty + 8 * j]);
}

// ---------------------------------------------------------------------------
// Half transpose (batched over z): src [z][R][C] -> dst [z][C][R], 64x64 tiles
// ---------------------------------------------------------------------------
__global__ __launch_bounds__(256)
void transpose_h64(const __half* __restrict__ src, __half* __restrict__ dst,
                   int R, int C)
{
    __shared__ __half t[64][65];
    const long zoff = (long)blockIdx.z * R * C;
    src += zoff; dst += zoff;
    const int tx = threadIdx.x, ty = threadIdx.y;
    const int xb = blockIdx.x * 64, yb = blockIdx.y * 64;
    #pragma unroll
    for (int j = 0; j < 8; j++) {
        int y = yb + ty + 8 * j;
        __half2 v = *reinterpret_cast<const __half2*>(&src[(long)y * C + xb + 2 * tx]);
        t[2 * tx][ty + 8 * j]     = __low2half(v);
        t[2 * tx + 1][ty + 8 * j] = __high2half(v);
    }
    __syncthreads();
    #pragma unroll
    for (int j = 0; j < 8; j++) {
        int c = ty + 8 * j;
        __half2 w = __halves2half2(t[c][2 * tx], t[c][2 * tx + 1]);
        *reinterpret_cast<__half2*>(&dst[(long)(xb + c) * R + yb + 2 * tx]) = w;
    }
}

// ---------------------------------------------------------------------------
// Row softmax over 2048-wide float rows -> half output
// ---------------------------------------------------------------------------
__global__ __launch_bounds__(256)
void softmax2048_h(const float* __restrict__ S, __half* __restrict__ P)
{
    const long row = blockIdx.x;
    const float* p = S + row * (long)LK;
    __half* q = P + row * (long)LK;
    const int tid = threadIdx.x;

    float4 a = reinterpret_cast<const float4*>(p)[tid];
    float4 b = reinterpret_cast<const float4*>(p)[tid + 256];

    float mx = fmaxf(fmaxf(fmaxf(a.x, a.y), fmaxf(a.z, a.w)),
                     fmaxf(fmaxf(b.x, b.y), fmaxf(b.z, b.w)));
    #pragma unroll
    for (int o = 16; o; o >>= 1) mx = fmaxf(mx, __shfl_xor_sync(0xffffffffu, mx, o));
    __shared__ float smax[8];
    if ((tid & 31) == 0) smax[tid >> 5] = mx;
    __syncthreads();
    mx = smax[0];
    #pragma unroll
    for (int i = 1; i < 8; i++) mx = fmaxf(mx, smax[i]);

    a.x = __expf(a.x - mx); a.y = __expf(a.y - mx);
    a.z = __expf(a.z - mx); a.w = __expf(a.w - mx);
    b.x = __expf(b.x - mx); b.y = __expf(b.y - mx);
    b.z = __expf(b.z - mx); b.w = __expf(b.w - mx);
    float sum = (a.x + a.y + a.z + a.w) + (b.x + b.y + b.z + b.w);
    #pragma unroll
    for (int o = 16; o; o >>= 1) sum += __shfl_xor_sync(0xffffffffu, sum, o);
    __shared__ float ssum[8];
    if ((tid & 31) == 0) ssum[tid >> 5] = sum;
    __syncthreads();
    sum = 0.f;
    #pragma unroll
    for (int i = 0; i < 8; i++) sum += ssum[i];

    const float inv = 1.0f / sum;
    __half2 h0 = __floats2half2_rn(a.x * inv, a.y * inv);
    __half2 h1 = __floats2half2_rn(a.z * inv, a.w * inv);
    __half2 h2 = __floats2half2_rn(b.x * inv, b.y * inv);
    __half2 h3 = __floats2half2_rn(b.z * inv, b.w * inv);
    uint2 u0, u1;
    u0.x = *reinterpret_cast<uint32_t*>(&h0);
    u0.y = *reinterpret_cast<uint32_t*>(&h1);
    u1.x = *reinterpret_cast<uint32_t*>(&h2);
    u1.y = *reinterpret_cast<uint32_t*>(&h3);
    reinterpret_cast<uint2*>(q)[tid]       = u0;
    reinterpret_cast<uint2*>(q)[tid + 256] = u1;
}

// ---------------------------------------------------------------------------
// Launch
// ---------------------------------------------------------------------------
extern "C" void kernel_launch(void* const* d_in, const int* in_sizes, int n_in,
                              void* d_out, int out_size)
{
    const float* img = (const float*)d_in[0];
    const float* txt = (const float*)d_in[1];
    const float* Wq  = (const float*)d_in[2];
    const float* bq  = (const float*)d_in[3];
    const float* Wk  = (const float*)d_in[4];
    const float* bk  = (const float*)d_in[5];
    const float* Wv  = (const float*)d_in[6];
    const float* bv  = (const float*)d_in[7];
    float* out = (float*)d_out;

    __half *imgh, *txth, *Wqt, *Wkt, *Wvt, *Qh, *Kh, *Vh, *Vt, *Pb;
    float *Sb;
    cudaGetSymbolAddress((void**)&imgh, g_img);
    cudaGetSymbolAddress((void**)&txth, g_txt);
    cudaGetSymbolAddress((void**)&Wqt, g_Wqt);
    cudaGetSymbolAddress((void**)&Wkt, g_Wkt);
    cudaGetSymbolAddress((void**)&Wvt, g_Wvt);
    cudaGetSymbolAddress((void**)&Qh, g_Qh);
    cudaGetSymbolAddress((void**)&Kh, g_Kh);
    cudaGetSymbolAddress((void**)&Vh, g_Vh);
    cudaGetSymbolAddress((void**)&Vt, g_Vt);
    cudaGetSymbolAddress((void**)&Sb, g_S);
    cudaGetSymbolAddress((void**)&Pb, g_P);

    const dim3 blk(256);

    // ---- convert activations to half ----
    {
        long n4 = (long)MQ * IMG_DIM / 4;
        f2h_kernel<<<(unsigned)((n4 + 255) / 256), blk>>>(img, imgh, n4);
        n4 = (long)MK * TXT_DIM / 4;
        f2h_kernel<<<(unsigned)((n4 + 255) / 256), blk>>>(txt, txth, n4);
    }

    // ---- transpose + convert weights: [K][HID] float -> [HID][K] half ----
    transpose_f2h<<<dim3(HID / 32, IMG_DIM / 32), dim3(32, 8)>>>(Wq, Wqt, IMG_DIM, HID);
    transpose_f2h<<<dim3(HID / 32, TXT_DIM / 32), dim3(32, 8)>>>(Wk, Wkt, TXT_DIM, HID);
    transpose_f2h<<<dim3(HID / 32, TXT_DIM / 32), dim3(32, 8)>>>(Wv, Wvt, TXT_DIM, HID);

    // ---- projections (NT, half out) ----
    gemm_f16_nt<true, true><<<dim3(HID / 128, MQ / 128, 1), blk>>>(
        imgh, Wqt, bq, Qh, IMG_DIM, IMG_DIM, IMG_DIM, HID, 0, 0, 0, 1.0f);
    gemm_f16_nt<true, true><<<dim3(HID / 128, MK / 128, 1), blk>>>(
        txth, Wkt, bk, Kh, TXT_DIM, TXT_DIM, TXT_DIM, HID, 0, 0, 0, 1.0f);
    gemm_f16_nt<true, true><<<dim3(HID / 128, MK / 128, 1), blk>>>(
        txth, Wvt, bv, Vh, TXT_DIM, TXT_DIM, TXT_DIM, HID, 0, 0, 0, 1.0f);

    // ---- V transpose: [z][LK][HID] -> [z][HID][LK] ----
    transpose_h64<<<dim3(HID / 64, LK / 64, BATCH), dim3(32, 8)>>>(Vh, Vt, LK, HID);

    // ---- attention in chunks of ZCHUNK batches ----
    for (int c = 0; c < NCHUNK; c++) {
        const long zoff = (long)c * ZCHUNK;
        // S = (1/sqrt(HID)) * Q @ K^T
        gemm_f16_nt<false, false><<<dim3(LK / 128, LQ / 128, ZCHUNK), blk>>>(
            Qh + zoff * LQ * HID, Kh + zoff * LK * HID, nullptr, Sb,
            HID, HID, HID, LK,
            (long)LQ * HID, (long)LK * HID, (long)LQ * LK, 0.03125f);
        // P = softmax(S) (half)
        softmax2048_h<<<ZCHUNK * LQ, blk>>>(Sb, Pb);
        // O = P @ Vt^T  (NT: Vt rows are HID dims, K-dim = LK)
        gemm_f16_nt<false, false><<<dim3(HID / 128, LQ / 128, ZCHUNK), blk>>>(
            Pb, Vt + zoff * HID * LK, nullptr, out + zoff * LQ * HID,
            LK, LK, LK, HID,
            (long)LQ * LK, (long)HID * LK, (long)LQ * HID, 1.0f);
    }
}

// round 9
// speedup vs baseline: 2.0082x; 1.1617x over previous
// R8 resubmit of the ldmatrix variant (R7/R8 container failures were infra;
// R4/R5 proved this error mode is content-independent).
#include <cuda_runtime.h>
#include <cuda_fp16.h>
#include <cstdint>

// ---------------------------------------------------------------------------
// Problem constants
// ---------------------------------------------------------------------------
#define BATCH   8
#define LQ      2048
#define LK      2048
#define IMG_DIM 1024
#define TXT_DIM 768
#define HID     1024

#define MQ (BATCH * LQ)
#define MK (BATCH * LK)

#define ZCHUNK  2
#define NCHUNK  (BATCH / ZCHUNK)

// ---------------------------------------------------------------------------
// Static scratch (~237 MB)
// ---------------------------------------------------------------------------
__device__ __half g_img[(size_t)MQ * IMG_DIM];
__device__ __half g_txt[(size_t)MK * TXT_DIM];
__device__ __half g_Wqt[(size_t)HID * IMG_DIM];
__device__ __half g_Wkt[(size_t)HID * TXT_DIM];
__device__ __half g_Wvt[(size_t)HID * TXT_DIM];
__device__ __half g_Qh[(size_t)MQ * HID];
__device__ __half g_Kh[(size_t)MK * HID];
__device__ __half g_Vh[(size_t)MK * HID];
__device__ __half g_Vt[(size_t)BATCH * HID * LK];
__device__ float  g_S[(size_t)ZCHUNK * LQ * LK];
__device__ __half g_P[(size_t)ZCHUNK * LQ * LK];

// ---------------------------------------------------------------------------
// Helpers
// ---------------------------------------------------------------------------
__device__ __forceinline__ void cp16(void* dst, const void* src) {
    uint32_t s = (uint32_t)__cvta_generic_to_shared(dst);
    asm volatile("cp.async.cg.shared.global [%0], [%1], 16;" :: "r"(s), "l"(src));
}
#define CP_COMMIT() asm volatile("cp.async.commit_group;")

__device__ __forceinline__ void mma_f16(float* d, const uint32_t* a, const uint32_t* b) {
    asm volatile(
        "mma.sync.aligned.m16n8k16.row.col.f32.f16.f16.f32 "
        "{%0,%1,%2,%3}, {%4,%5,%6,%7}, {%8,%9}, {%0,%1,%2,%3};"
        : "+f"(d[0]), "+f"(d[1]), "+f"(d[2]), "+f"(d[3])
        : "r"(a[0]), "r"(a[1]), "r"(a[2]), "r"(a[3]),
          "r"(b[0]), "r"(b[1]));
}

__device__ __forceinline__ void ldsm_x4(uint32_t& r0, uint32_t& r1,
                                        uint32_t& r2, uint32_t& r3, uint32_t addr) {
    asm volatile("ldmatrix.sync.aligned.m8n8.x4.shared.b16 {%0,%1,%2,%3}, [%4];"
                 : "=r"(r0), "=r"(r1), "=r"(r2), "=r"(r3) : "r"(addr));
}

// ---------------------------------------------------------------------------
// FP16 NT GEMM: C[z] = alpha * A[z] @ B[z]^T (+ bias)
//   A row-major [M][K] half, B row-major [N][K] half (both K-contiguous).
// Tile BM=BN=128, BK=32; 256 threads (8 warps, 4M x 2N, warp 32x64);
// cp.async double-buffered; ldmatrix fragment loads.
// Requires M,N % 128 == 0, K % 32 == 0, lda/ldb % 8 == 0.
// ---------------------------------------------------------------------------
template <bool HAS_BIAS, bool OUT_HALF>
__global__ __launch_bounds__(256, 2)
void gemm_f16_nt(const __half* __restrict__ A, const __half* __restrict__ B,
                 const float* __restrict__ bias, void* __restrict__ Cv,
                 int K, int lda, int ldb, int ldc,
                 long sA, long sB, long sC, float alpha)
{
    constexpr int BM = 128, BN = 128, BK = 32, LDT = 40;  // 40-half row stride (80 B)
    __shared__ __half As[2][BM][LDT];
    __shared__ __half Bs[2][BN][LDT];

    const int bz = blockIdx.z;
    A += (long)bz * sA;
    B += (long)bz * sB;

    const int m0 = blockIdx.y * BM;
    const int n0 = blockIdx.x * BN;

    const int tid  = threadIdx.x;
    const int lane = tid & 31;
    const int warp = tid >> 5;
    const int gid  = lane >> 2;
    const int tid4 = lane & 3;
    const int wm   = warp & 3;
    const int wn   = warp >> 2;

    // gmem -> smem loaders: row = tid>>1, two 16B chunks at (tid&1)*2
    const int r_ld = tid >> 1;
    const int s_ld = (tid & 1) * 2;

    // ldmatrix per-lane source rows/cols (byte offsets within a [128][LDT] tile)
    // A (.x4): mats = (mlo,klo),(mhi,klo),(mlo,khi),(mhi,khi)
    //   row bit: lane bit3 -> +8 rows ; k bit: lane bit4 -> +8 cols
    const int a_row = (lane & 7) + ((lane >> 3) & 1) * 8;   // within m16
    const int a_kof = ((lane >> 4) & 1) * 8;                // within k16
    // B (.x4): mats = (nlo,klo),(nlo,khi),(nhi,klo),(nhi,khi)
    //   row bit: lane bit4 -> +8 rows ; k bit: lane bit3 -> +8 cols
    const int b_row = (lane & 7) + ((lane >> 4) & 1) * 8;   // within n16
    const int b_kof = ((lane >> 3) & 1) * 8;                // within k16

    const uint32_t as_base = (uint32_t)__cvta_generic_to_shared(&As[0][0][0]);
    const uint32_t bs_base = (uint32_t)__cvta_generic_to_shared(&Bs[0][0][0]);
    const uint32_t stage_sz = BM * LDT * 2;                 // bytes per stage

    // per-thread fixed components of ldmatrix addresses
    uint32_t a_off[2];                                      // per mt
    #pragma unroll
    for (int mt = 0; mt < 2; mt++)
        a_off[mt] = ((wm * 32 + mt * 16 + a_row) * LDT + a_kof) * 2;
    uint32_t b_off[4];                                      // per nt-pair
    #pragma unroll
    for (int np = 0; np < 4; np++)
        b_off[np] = ((wn * 64 + np * 16 + b_row) * LDT + b_kof) * 2;

    float acc[2][8][4] = {};
    const int nk = K / BK;

    // prologue: tile 0
    {
        const __half* a0 = A + (long)(m0 + r_ld) * lda + s_ld * 8;
        const __half* b0 = B + (long)(n0 + r_ld) * ldb + s_ld * 8;
        cp16(&As[0][r_ld][s_ld * 8],      a0);
        cp16(&As[0][r_ld][s_ld * 8 + 8],  a0 + 8);
        cp16(&Bs[0][r_ld][s_ld * 8],      b0);
        cp16(&Bs[0][r_ld][s_ld * 8 + 8],  b0 + 8);
    }
    CP_COMMIT();

    for (int kt = 0; kt < nk; kt++) {
        const int cur = kt & 1;
        if (kt + 1 < nk) {
            const int k0 = (kt + 1) * BK;
            const __half* a0 = A + (long)(m0 + r_ld) * lda + k0 + s_ld * 8;
            const __half* b0 = B + (long)(n0 + r_ld) * ldb + k0 + s_ld * 8;
            cp16(&As[cur ^ 1][r_ld][s_ld * 8],     a0);
            cp16(&As[cur ^ 1][r_ld][s_ld * 8 + 8], a0 + 8);
            cp16(&Bs[cur ^ 1][r_ld][s_ld * 8],     b0);
            cp16(&Bs[cur ^ 1][r_ld][s_ld * 8 + 8], b0 + 8);
        }
        CP_COMMIT();
        asm volatile("cp.async.wait_group 1;");
        __syncthreads();

        const uint32_t a_st = as_base + cur * stage_sz;
        const uint32_t b_st = bs_base + cur * stage_sz;

        #pragma unroll
        for (int ks = 0; ks < 2; ks++) {
            const uint32_t kb = ks * 16 * 2;     // k16-step byte offset
            uint32_t af[2][4], bf[8][2];
            #pragma unroll
            for (int mt = 0; mt < 2; mt++)
                ldsm_x4(af[mt][0], af[mt][1], af[mt][2], af[mt][3],
                        a_st + a_off[mt] + kb);
            #pragma unroll
            for (int np = 0; np < 4; np++)
                ldsm_x4(bf[2*np][0], bf[2*np][1], bf[2*np+1][0], bf[2*np+1][1],
                        b_st + b_off[np] + kb);
            #pragma unroll
            for (int mt = 0; mt < 2; mt++)
                #pragma unroll
                for (int nt = 0; nt < 8; nt++)
                    mma_f16(acc[mt][nt], af[mt], bf[nt]);
        }
        __syncthreads();
    }

    // ---- epilogue ----
    #pragma unroll
    for (int mt = 0; mt < 2; mt++) {
        #pragma unroll
        for (int nt = 0; nt < 8; nt++) {
            const int col = n0 + wn * 64 + nt * 8 + 2 * tid4;
            float b0 = 0.f, b1 = 0.f;
            if (HAS_BIAS) { b0 = bias[col]; b1 = bias[col + 1]; }
            const int r0 = m0 + wm * 32 + mt * 16 + gid;
            float v00 = alpha * acc[mt][nt][0] + b0;
            float v01 = alpha * acc[mt][nt][1] + b1;
            float v10 = alpha * acc[mt][nt][2] + b0;
            float v11 = alpha * acc[mt][nt][3] + b1;
            if (OUT_HALF) {
                __half* C = (__half*)Cv + (long)bz * sC;
                __half2 h0 = __floats2half2_rn(v00, v01);
                __half2 h1 = __floats2half2_rn(v10, v11);
                *reinterpret_cast<__half2*>(&C[(long)r0 * ldc + col])       = h0;
                *reinterpret_cast<__half2*>(&C[(long)(r0 + 8) * ldc + col]) = h1;
            } else {
                float* C = (float*)Cv + (long)bz * sC;
                *reinterpret_cast<float2*>(&C[(long)r0 * ldc + col])       = make_float2(v00, v01);
                *reinterpret_cast<float2*>(&C[(long)(r0 + 8) * ldc + col]) = make_float2(v10, v11);
            }
        }
    }
}

// ---------------------------------------------------------------------------
// float -> half elementwise
// ---------------------------------------------------------------------------
__global__ __launch_bounds__(256)
void f2h_kernel(const float* __restrict__ s, __half* __restrict__ d, long n4)
{
    long i = blockIdx.x * (long)blockDim.x + threadIdx.x;
    if (i < n4) {
        float4 v = reinterpret_cast<const float4*>(s)[i];
        __half2 h0 = __floats2half2_rn(v.x, v.y);
        __half2 h1 = __floats2half2_rn(v.z, v.w);
        uint2 u;
        u.x = *reinterpret_cast<uint32_t*>(&h0);
        u.y = *reinterpret_cast<uint32_t*>(&h1);
        reinterpret_cast<uint2*>(d)[i] = u;
    }
}

// ---------------------------------------------------------------------------
// Weight transpose + convert: src float [R][C] -> dst half [C][R]
// ---------------------------------------------------------------------------
__global__ __launch_bounds__(256)
void transpose_f2h(const float* __restrict__ src, __half* __restrict__ dst,
                   int R, int C)
{
    __shared__ float t[32][33];
    const int tx = threadIdx.x, ty = threadIdx.y;
    const int xb = blockIdx.x * 32, yb = blockIdx.y * 32;
    #pragma unroll
    for (int j = 0; j < 4; j++)
        t[ty + 8 * j][tx] = src[(long)(yb + ty + 8 * j) * C + xb + tx];
    __syncthreads();
    #pragma unroll
    for (int j = 0; j < 4; j++)
        dst[(long)(xb + ty + 8 * j) * R + yb + tx] = __float2half(t[tx][ty + 8 * j]);
}

// ---------------------------------------------------------------------------
// Half transpose (batched): src [z][R][C] -> dst [z][C][R]
// ---------------------------------------------------------------------------
__global__ __launch_bounds__(256)
void transpose_h64(const __half* __restrict__ src, __half* __restrict__ dst,
                   int R, int C)
{
    __shared__ __half t[64][65];
    const long zoff = (long)blockIdx.z * R * C;
    src += zoff; dst += zoff;
    const int tx = threadIdx.x, ty = threadIdx.y;
    const int xb = blockIdx.x * 64, yb = blockIdx.y * 64;
    #pragma unroll
    for (int j = 0; j < 8; j++) {
        int y = yb + ty + 8 * j;
        __half2 v = *reinterpret_cast<const __half2*>(&src[(long)y * C + xb + 2 * tx]);
        t[2 * tx][ty + 8 * j]     = __low2half(v);
        t[2 * tx + 1][ty + 8 * j] = __high2half(v);
    }
    __syncthreads();
    #pragma unroll
    for (int j = 0; j < 8; j++) {
        int c = ty + 8 * j;
        __half2 w = __halves2half2(t[c][2 * tx], t[c][2 * tx + 1]);
        *reinterpret_cast<__half2*>(&dst[(long)(xb + c) * R + yb + 2 * tx]) = w;
    }
}

// ---------------------------------------------------------------------------
// Row softmax over 2048-wide float rows -> half output
// ---------------------------------------------------------------------------
__global__ __launch_bounds__(256)
void softmax2048_h(const float* __restrict__ S, __half* __restrict__ P)
{
    const long row = blockIdx.x;
    const float* p = S + row * (long)LK;
    __half* q = P + row * (long)LK;
    const int tid = threadIdx.x;

    float4 a = reinterpret_cast<const float4*>(p)[tid];
    float4 b = reinterpret_cast<const float4*>(p)[tid + 256];

    float mx = fmaxf(fmaxf(fmaxf(a.x, a.y), fmaxf(a.z, a.w)),
                     fmaxf(fmaxf(b.x, b.y), fmaxf(b.z, b.w)));
    #pragma unroll
    for (int o = 16; o; o >>= 1) mx = fmaxf(mx, __shfl_xor_sync(0xffffffffu, mx, o));
    __shared__ float smax[8];
    if ((tid & 31) == 0) smax[tid >> 5] = mx;
    __syncthreads();
    mx = smax[0];
    #pragma unroll
    for (int i = 1; i < 8; i++) mx = fmaxf(mx, smax[i]);

    a.x = __expf(a.x - mx); a.y = __expf(a.y - mx);
    a.z = __expf(a.z - mx); a.w = __expf(a.w - mx);
    b.x = __expf(b.x - mx); b.y = __expf(b.y - mx);
    b.z = __expf(b.z - mx); b.w = __expf(b.w - mx);
    float sum = (a.x + a.y + a.z + a.w) + (b.x + b.y + b.z + b.w);
    #pragma unroll
    for (int o = 16; o; o >>= 1) sum += __shfl_xor_sync(0xffffffffu, sum, o);
    __shared__ float ssum[8];
    if ((tid & 31) == 0) ssum[tid >> 5] = sum;
    __syncthreads();
    sum = 0.f;
    #pragma unroll
    for (int i = 0; i < 8; i++) sum += ssum[i];

    const float inv = 1.0f / sum;
    __half2 h0 = __floats2half2_rn(a.x * inv, a.y * inv);
    __half2 h1 = __floats2half2_rn(a.z * inv, a.w * inv);
    __half2 h2 = __floats2half2_rn(b.x * inv, b.y * inv);
    __half2 h3 = __floats2half2_rn(b.z * inv, b.w * inv);
    uint2 u0, u1;
    u0.x = *reinterpret_cast<uint32_t*>(&h0);
    u0.y = *reinterpret_cast<uint32_t*>(&h1);
    u1.x = *reinterpret_cast<uint32_t*>(&h2);
    u1.y = *reinterpret_cast<uint32_t*>(&h3);
    reinterpret_cast<uint2*>(q)[tid]       = u0;
    reinterpret_cast<uint2*>(q)[tid + 256] = u1;
}

// ---------------------------------------------------------------------------
// Launch
// ---------------------------------------------------------------------------
extern "C" void kernel_launch(void* const* d_in, const int* in_sizes, int n_in,
                              void* d_out, int out_size)
{
    const float* img = (const float*)d_in[0];
    const float* txt = (const float*)d_in[1];
    const float* Wq  = (const float*)d_in[2];
    const float* bq  = (const float*)d_in[3];
    const float* Wk  = (const float*)d_in[4];
    const float* bk  = (const float*)d_in[5];
    const float* Wv  = (const float*)d_in[6];
    const float* bv  = (const float*)d_in[7];
    float* out = (float*)d_out;

    __half *imgh, *txth, *Wqt, *Wkt, *Wvt, *Qh, *Kh, *Vh, *Vt, *Pb;
    float *Sb;
    cudaGetSymbolAddress((void**)&imgh, g_img);
    cudaGetSymbolAddress((void**)&txth, g_txt);
    cudaGetSymbolAddress((void**)&Wqt, g_Wqt);
    cudaGetSymbolAddress((void**)&Wkt, g_Wkt);
    cudaGetSymbolAddress((void**)&Wvt, g_Wvt);
    cudaGetSymbolAddress((void**)&Qh, g_Qh);
    cudaGetSymbolAddress((void**)&Kh, g_Kh);
    cudaGetSymbolAddress((void**)&Vh, g_Vh);
    cudaGetSymbolAddress((void**)&Vt, g_Vt);
    cudaGetSymbolAddress((void**)&Sb, g_S);
    cudaGetSymbolAddress((void**)&Pb, g_P);

    const dim3 blk(256);

    // ---- convert activations to half ----
    {
        long n4 = (long)MQ * IMG_DIM / 4;
        f2h_kernel<<<(unsigned)((n4 + 255) / 256), blk>>>(img, imgh, n4);
        n4 = (long)MK * TXT_DIM / 4;
        f2h_kernel<<<(unsigned)((n4 + 255) / 256), blk>>>(txt, txth, n4);
    }

    // ---- transpose + convert weights: [K][HID] float -> [HID][K] half ----
    transpose_f2h<<<dim3(HID / 32, IMG_DIM / 32), dim3(32, 8)>>>(Wq, Wqt, IMG_DIM, HID);
    transpose_f2h<<<dim3(HID / 32, TXT_DIM / 32), dim3(32, 8)>>>(Wk, Wkt, TXT_DIM, HID);
    transpose_f2h<<<dim3(HID / 32, TXT_DIM / 32), dim3(32, 8)>>>(Wv, Wvt, TXT_DIM, HID);

    // ---- projections (NT, half out) ----
    gemm_f16_nt<true, true><<<dim3(HID / 128, MQ / 128, 1), blk>>>(
        imgh, Wqt, bq, Qh, IMG_DIM, IMG_DIM, IMG_DIM, HID, 0, 0, 0, 1.0f);
    gemm_f16_nt<true, true><<<dim3(HID / 128, MK / 128, 1), blk>>>(
        txth, Wkt, bk, Kh, TXT_DIM, TXT_DIM, TXT_DIM, HID, 0, 0, 0, 1.0f);
    gemm_f16_nt<true, true><<<dim3(HID / 128, MK / 128, 1), blk>>>(
        txth, Wvt, bv, Vh, TXT_DIM, TXT_DIM, TXT_DIM, HID, 0, 0, 0, 1.0f);

    // ---- V transpose: [z][LK][HID] -> [z][HID][LK] ----
    transpose_h64<<<dim3(HID / 64, LK / 64, BATCH), dim3(32, 8)>>>(Vh, Vt, LK, HID);

    // ---- attention in chunks of ZCHUNK batches ----
    for (int c = 0; c < NCHUNK; c++) {
        const long zoff = (long)c * ZCHUNK;
        // S = (1/sqrt(HID)) * Q @ K^T
        gemm_f16_nt<false, false><<<dim3(LK / 128, LQ / 128, ZCHUNK), blk>>>(
            Qh + zoff * LQ * HID, Kh + zoff * LK * HID, nullptr, Sb,
            HID, HID, HID, LK,
            (long)LQ * HID, (long)LK * HID, (long)LQ * LK, 0.03125f);
        // P = softmax(S) (half)
        softmax2048_h<<<ZCHUNK * LQ, blk>>>(Sb, Pb);
        // O = P @ Vt^T
        gemm_f16_nt<false, false><<<dim3(HID / 128, LQ / 128, ZCHUNK), blk>>>(
            Pb, Vt + zoff * HID * LK, nullptr, out + zoff * LQ * HID,
            LK, LK, LK, HID,
            (long)LQ * LK, (long)HID * LK, (long)LQ * HID, 1.0f);
    }
}